// round 15
// baseline (speedup 1.0000x reference)
#include <cuda_runtime.h>
#include <cuda_bf16.h>
#include <cstdint>

#define D     128
#define NS    50000
#define NDST  50000
#define NE    640000
#define NPERS 296   // persistent grid: 148 SMs x 2 CTAs

// ---------------- scratch (static device arrays; no allocation) ----------------
__device__ __align__(16) float          g_hs[NS * D];
__device__ __align__(16) float          g_hd[NDST * D];
__device__ __align__(16) float          g_nf[NDST * D];
__device__ float          g_s[NE];
__device__ float          g_denom[NDST];
__device__ unsigned       g_mkey[NDST];
// 4 pre-split transposed weights: [which][n][k], bf16 hi/lo
__device__ __align__(16) __nv_bfloat16  g_whi[4 * D * D];
__device__ __align__(16) __nv_bfloat16  g_wlo[4 * D * D];

__device__ __forceinline__ float lrelu(float x) { return x > 0.f ? x : 0.01f * x; }

__device__ __forceinline__ unsigned fenc(float f) {
    unsigned u = __float_as_uint(f);
    return (u & 0x80000000u) ? ~u : (u | 0x80000000u);
}
__device__ __forceinline__ float fdec(unsigned u) {
    return __uint_as_float((u & 0x80000000u) ? (u & 0x7FFFFFFFu) : ~u);
}

// ---------------- warp-mma helpers (generic PTX: sm_80+) ----------------
__device__ __forceinline__ uint32_t smem_u32(const void* p) {
    return (uint32_t)__cvta_generic_to_shared(p);
}
__device__ __forceinline__ void ldsm4(uint32_t* r, uint32_t addr) {
    asm volatile("ldmatrix.sync.aligned.m8n8.x4.shared.b16 {%0,%1,%2,%3}, [%4];"
                 : "=r"(r[0]), "=r"(r[1]), "=r"(r[2]), "=r"(r[3]) : "r"(addr));
}
__device__ __forceinline__ void mma16816(float* c, const uint32_t* a, const uint32_t* b) {
    asm volatile("mma.sync.aligned.m16n8k16.row.col.f32.bf16.bf16.f32 "
                 "{%0,%1,%2,%3}, {%4,%5,%6,%7}, {%8,%9}, {%0,%1,%2,%3};"
                 : "+f"(c[0]), "+f"(c[1]), "+f"(c[2]), "+f"(c[3])
                 : "r"(a[0]), "r"(a[1]), "r"(a[2]), "r"(a[3]), "r"(b[0]), "r"(b[1]));
}
// split two fp32 into packed bf16x2 hi / lo (error compensation)
__device__ __forceinline__ void split2(float x, float y, uint32_t& h, uint32_t& l) {
    __nv_bfloat16 hx = __float2bfloat16(x);
    __nv_bfloat16 hy = __float2bfloat16(y);
    __nv_bfloat16 lx = __float2bfloat16(x - __bfloat162float(hx));
    __nv_bfloat16 ly = __float2bfloat16(y - __bfloat162float(hy));
    h = ((uint32_t)__bfloat16_as_ushort(hy) << 16) | __bfloat16_as_ushort(hx);
    l = ((uint32_t)__bfloat16_as_ushort(ly) << 16) | __bfloat16_as_ushort(lx);
}
// swizzled byte offset of 16B unit (row, colUnit) in a [rows][128 bf16] tile (256B rows)
__device__ __forceinline__ uint32_t uoff(int r, int cu) {
    return (uint32_t)(r * 256 + ((cu ^ (r & 7)) << 4));
}

// smem: B tiles only
#define SMB_HI  0
#define SMB_LO  32768
#define SMB_AUX 65536
#define SMEM_SZ (65536 + 1024)

// ---------------- init ----------------
__global__ void k_init_nf() {
    int i = blockIdx.x * blockDim.x + threadIdx.x;
    if (i < NDST * D) g_nf[i] = 0.f;
}
__global__ void k_init_seg() {
    int i = blockIdx.x * blockDim.x + threadIdx.x;
    if (i < NDST) { g_denom[i] = 0.f; g_mkey[i] = 0u; }
}

// ---------------- prep: split all 4 W^T into bf16 hi/lo, [n][k] layout ----------------
__global__ void k_prep(const float* __restrict__ W0, const float* __restrict__ W1,
                       const float* __restrict__ W2, const float* __restrict__ W3)
{
    int i = blockIdx.x * blockDim.x + threadIdx.x;
    if (i >= 4 * D * D) return;
    int which = i >> 14;
    int j = i & (D * D - 1);
    int n = j >> 7, k = j & 127;
    const float* W = which == 0 ? W0 : which == 1 ? W1 : which == 2 ? W2 : W3;
    float w = W[k * D + n];
    __nv_bfloat16 hi = __float2bfloat16(w);
    __nv_bfloat16 lo = __float2bfloat16(w - __bfloat162float(hi));
    g_whi[i] = hi;
    g_wlo[i] = lo;
}

// ---- shared mainloop body: batched ldsm + round-robin MMA over 8 accumulators ----
#define MAINLOOP_KK(c, Ahi_k, Alo_k)                                              \
    do {                                                                          \
        uint32_t bf[4][4];                                                        \
        _Pragma("unroll")                                                         \
        for (int p = 0; p < 4; p++) {                                             \
            int rowB = h * 64 + p * 16 + rBoff;                                   \
            uint32_t bo = (uint32_t)(rowB * 256 + (((kk * 2 + cB2) ^ rxB) << 4)); \
            ldsm4(bf[p], bhiB + bo);                                              \
        }                                                                         \
        _Pragma("unroll")                                                         \
        for (int p = 0; p < 4; p++) {                                             \
            mma16816(c[2 * p],     Ahi_k, bf[p]);                                 \
            mma16816(c[2 * p + 1], Ahi_k, bf[p] + 2);                             \
        }                                                                         \
        _Pragma("unroll")                                                         \
        for (int p = 0; p < 4; p++) {                                             \
            mma16816(c[2 * p],     Alo_k, bf[p]);                                 \
            mma16816(c[2 * p + 1], Alo_k, bf[p] + 2);                             \
        }                                                                         \
        _Pragma("unroll")                                                         \
        for (int p = 0; p < 4; p++) {                                             \
            int rowB = h * 64 + p * 16 + rBoff;                                   \
            uint32_t bo = (uint32_t)(rowB * 256 + (((kk * 2 + cB2) ^ rxB) << 4)); \
            ldsm4(bf[p], bloB + bo);                                              \
        }                                                                         \
        _Pragma("unroll")                                                         \
        for (int p = 0; p < 4; p++) {                                             \
            mma16816(c[2 * p],     Ahi_k, bf[p]);                                 \
            mma16816(c[2 * p + 1], Ahi_k, bf[p] + 2);                             \
        }                                                                         \
    } while (0)

// ---------------- persistent dense GEMM: stage B once, grid-stride over row tiles ----------------
// FINAL mode: Arow = nf*(1/denom) + hd (gated on denom>0), act = lrelu.
template<bool FINAL>
__global__ __launch_bounds__(256, 2) void k_gemm2(
    const float* __restrict__ A, const float* __restrict__ A2,
    const float* __restrict__ denom,
    const __nv_bfloat16* __restrict__ wh, const __nv_bfloat16* __restrict__ wl,
    const float* __restrict__ bias, float* __restrict__ C, int M)
{
    extern __shared__ char sm[];
    char*  Bhi = sm + SMB_HI;
    char*  Blo = sm + SMB_LO;
    float* sB  = (float*)(sm + SMB_AUX);

    int t = threadIdx.x, lane = t & 31, w = t >> 5;

    if (t < 128) sB[t] = bias[t];
    for (int i = t; i < 2048; i += 256) {
        int n = i >> 4, cu = i & 15;
        *(uint4*)(Bhi + uoff(n, cu)) = *(const uint4*)(wh + n * 128 + cu * 8);
        *(uint4*)(Blo + uoff(n, cu)) = *(const uint4*)(wl + n * 128 + cu * 8);
    }
    __syncthreads();

    int rBoff = ((lane >> 4) << 3) + (lane & 7);
    int cB2   = (lane >> 3) & 1;
    int rxB   = lane & 7;
    uint32_t bhiB = smem_u32(Bhi), bloB = smem_u32(Blo);
    int cbase = (lane & 3) * 2;
    int nTiles = (M + 127) >> 7;

    for (int tile = blockIdx.x; tile < nTiles; tile += NPERS) {
        int m0 = tile << 7;
        int r0 = m0 + w * 16 + (lane >> 2);
        int r1 = r0 + 8;
        bool v0 = r0 < M, v1 = r1 < M;

        float sc0 = 1.f, sc1 = 1.f;
        bool add0 = false, add1 = false;
        if (FINAL) {
            float den0 = v0 ? __ldg(denom + r0) : 0.f;
            float den1 = v1 ? __ldg(denom + r1) : 0.f;
            add0 = den0 > 0.f; add1 = den1 > 0.f;
            sc0 = add0 ? 1.f / den0 : 0.f;
            sc1 = add1 ? 1.f / den1 : 0.f;
        }

        const float* a0p = A + (size_t)r0 * 128;
        const float* a1p = A + (size_t)r1 * 128;

        uint32_t Ahi[8][4], Alo[8][4];
#pragma unroll
        for (int k = 0; k < 8; k++) {
            int c0 = k * 16 + cbase, c1 = c0 + 8;
            float2 x00 = make_float2(0.f, 0.f), x10 = x00, x01 = x00, x11 = x00;
            if (v0) { x00 = *(const float2*)(a0p + c0); x01 = *(const float2*)(a0p + c1); }
            if (v1) { x10 = *(const float2*)(a1p + c0); x11 = *(const float2*)(a1p + c1); }
            if (FINAL) {
                const float* h0p = A2 + (size_t)r0 * 128;
                const float* h1p = A2 + (size_t)r1 * 128;
                float2 y00 = make_float2(0.f, 0.f), y10 = y00, y01 = y00, y11 = y00;
                if (add0) { y00 = *(const float2*)(h0p + c0); y01 = *(const float2*)(h0p + c1); }
                if (add1) { y10 = *(const float2*)(h1p + c0); y11 = *(const float2*)(h1p + c1); }
                x00.x = x00.x * sc0 + y00.x; x00.y = x00.y * sc0 + y00.y;
                x01.x = x01.x * sc0 + y01.x; x01.y = x01.y * sc0 + y01.y;
                x10.x = x10.x * sc1 + y10.x; x10.y = x10.y * sc1 + y10.y;
                x11.x = x11.x * sc1 + y11.x; x11.y = x11.y * sc1 + y11.y;
            }
            split2(x00.x, x00.y, Ahi[k][0], Alo[k][0]);
            split2(x10.x, x10.y, Ahi[k][1], Alo[k][1]);
            split2(x01.x, x01.y, Ahi[k][2], Alo[k][2]);
            split2(x11.x, x11.y, Ahi[k][3], Alo[k][3]);
        }

#pragma unroll
        for (int h = 0; h < 2; h++) {
            float c[8][4];
#pragma unroll
            for (int n2 = 0; n2 < 8; n2++)
#pragma unroll
                for (int q = 0; q < 4; q++) c[n2][q] = 0.f;

#pragma unroll
            for (int kk = 0; kk < 8; kk++) {
                MAINLOOP_KK(c, Ahi[kk], Alo[kk]);
            }
#pragma unroll
            for (int n2 = 0; n2 < 8; n2++) {
                int n0 = (h * 8 + n2) * 8 + cbase;
                float b0 = sB[n0], b1 = sB[n0 + 1];
                float v00 = c[n2][0] + b0, v01 = c[n2][1] + b1;
                float v10 = c[n2][2] + b0, v11 = c[n2][3] + b1;
                if (FINAL) { v00 = lrelu(v00); v01 = lrelu(v01); v10 = lrelu(v10); v11 = lrelu(v11); }
                if (v0) *(float2*)(C + (size_t)r0 * 128 + n0) = make_float2(v00, v01);
                if (v1) *(float2*)(C + (size_t)r1 * 128 + n0) = make_float2(v10, v11);
            }
        }
    }
}

// ---------------- persistent edge score: stage W_a1 once, grid-stride over 128-edge tiles ----------------
__global__ __launch_bounds__(256, 2) void k_edge2(
    const int* __restrict__ src_idx, const int* __restrict__ dst_idx,
    const __nv_bfloat16* __restrict__ wh, const __nv_bfloat16* __restrict__ wl,
    const float* __restrict__ b_a1, const float* __restrict__ W_a2,
    const float* __restrict__ b_a2)
{
    extern __shared__ char sm[];
    char*  Bhi  = sm + SMB_HI;
    char*  Blo  = sm + SMB_LO;
    float* sBa1 = (float*)(sm + SMB_AUX);
    float* sWa2 = (float*)(sm + SMB_AUX + 512);

    int t = threadIdx.x, lane = t & 31, w = t >> 5;

    if (t < 128) { sBa1[t] = b_a1[t]; sWa2[t] = W_a2[t]; }
    for (int i = t; i < 2048; i += 256) {
        int n = i >> 4, cu = i & 15;
        *(uint4*)(Bhi + uoff(n, cu)) = *(const uint4*)(wh + n * 128 + cu * 8);
        *(uint4*)(Blo + uoff(n, cu)) = *(const uint4*)(wl + n * 128 + cu * 8);
    }
    __syncthreads();

    int rBoff = ((lane >> 4) << 3) + (lane & 7);
    int cB2   = (lane >> 3) & 1;
    int rxB   = lane & 7;
    uint32_t bhiB = smem_u32(Bhi), bloB = smem_u32(Blo);
    int cbase = (lane & 3) * 2;
    float ba2 = __ldg(b_a2);

    for (int tile = blockIdx.x; tile < NE / 128; tile += NPERS) {
        int e0 = tile << 7;
        int r0 = w * 16 + (lane >> 2);
        int r1 = r0 + 8;
        int s0 = __ldg(src_idx + e0 + r0), s1 = __ldg(src_idx + e0 + r1);
        int d0 = __ldg(dst_idx + e0 + r0), d1 = __ldg(dst_idx + e0 + r1);

        const float* hs0 = g_hs + (size_t)s0 * 128;
        const float* hs1 = g_hs + (size_t)s1 * 128;
        const float* hd0 = g_hd + (size_t)d0 * 128;
        const float* hd1 = g_hd + (size_t)d1 * 128;

        uint32_t Ahi[8][4], Alo[8][4];
#pragma unroll
        for (int k = 0; k < 8; k++) {
            int c0 = k * 16 + cbase, c1 = c0 + 8;
            float2 a00 = *(const float2*)(hs0 + c0), b00 = *(const float2*)(hd0 + c0);
            float2 a10 = *(const float2*)(hs1 + c0), b10 = *(const float2*)(hd1 + c0);
            float2 a01 = *(const float2*)(hs0 + c1), b01 = *(const float2*)(hd0 + c1);
            float2 a11 = *(const float2*)(hs1 + c1), b11 = *(const float2*)(hd1 + c1);
            split2(lrelu(a00.x + b00.x), lrelu(a00.y + b00.y), Ahi[k][0], Alo[k][0]);
            split2(lrelu(a10.x + b10.x), lrelu(a10.y + b10.y), Ahi[k][1], Alo[k][1]);
            split2(lrelu(a01.x + b01.x), lrelu(a01.y + b01.y), Ahi[k][2], Alo[k][2]);
            split2(lrelu(a11.x + b11.x), lrelu(a11.y + b11.y), Ahi[k][3], Alo[k][3]);
        }

        float rs0 = 0.f, rs1 = 0.f;

#pragma unroll
        for (int h = 0; h < 2; h++) {
            float c[8][4];
#pragma unroll
            for (int n2 = 0; n2 < 8; n2++)
#pragma unroll
                for (int q = 0; q < 4; q++) c[n2][q] = 0.f;

#pragma unroll
            for (int kk = 0; kk < 8; kk++) {
                MAINLOOP_KK(c, Ahi[kk], Alo[kk]);
            }
#pragma unroll
            for (int n2 = 0; n2 < 8; n2++) {
                int n0 = (h * 8 + n2) * 8 + cbase;
                float b0 = sBa1[n0], b1 = sBa1[n0 + 1];
                float w0 = sWa2[n0], w1 = sWa2[n0 + 1];
                rs0 += lrelu(c[n2][0] + b0) * w0 + lrelu(c[n2][1] + b1) * w1;
                rs1 += lrelu(c[n2][2] + b0) * w0 + lrelu(c[n2][3] + b1) * w1;
            }
        }

        rs0 += __shfl_xor_sync(0xffffffffu, rs0, 1);
        rs0 += __shfl_xor_sync(0xffffffffu, rs0, 2);
        rs1 += __shfl_xor_sync(0xffffffffu, rs1, 1);
        rs1 += __shfl_xor_sync(0xffffffffu, rs1, 2);

        if ((lane & 3) == 0) {
            float sv0 = rs0 + ba2, sv1 = rs1 + ba2;
            g_s[e0 + r0] = sv0;
            g_s[e0 + r1] = sv1;
            atomicMax(&g_mkey[d0], fenc(sv0));
            atomicMax(&g_mkey[d1], fenc(sv1));
        }
    }
}

// ---------------- fused exp + aggregation: nf[d] += ex*hs[src]; denom[d] += ex ----------------
__global__ __launch_bounds__(256) void k_agg2(
    const int* __restrict__ src_idx, const int* __restrict__ dst_idx)
{
    int gt   = blockIdx.x * blockDim.x + threadIdx.x;
    int e    = gt >> 5;
    int lane = gt & 31;
    if (e >= NE) return;
    int s = __ldg(src_idx + e), d = __ldg(dst_idx + e);
    float ex = expf(__ldg(g_s + e) - fdec(g_mkey[d]));
    if (lane == 0) atomicAdd(&g_denom[d], ex);

    const float4* hs4 = (const float4*)g_hs;
    float4 a = hs4[s * 32 + lane];
    float4 v = make_float4(ex * a.x, ex * a.y, ex * a.z, ex * a.w);

    float* p = g_nf + d * 128 + lane * 4;
    asm volatile("red.global.add.v4.f32 [%0], {%1, %2, %3, %4};"
                 :: "l"(p), "f"(v.x), "f"(v.y), "f"(v.z), "f"(v.w) : "memory");
}

// ---------------- launch ----------------
extern "C" void kernel_launch(void* const* d_in, const int* in_sizes, int n_in,
                              void* d_out, int out_size)
{
    const float* feat_src = (const float*)d_in[0];
    const float* feat_dst = (const float*)d_in[1];
    const int*   src_idx  = (const int*)d_in[2];
    const int*   dst_idx  = (const int*)d_in[3];
    const float* W_src    = (const float*)d_in[4];
    const float* b_src    = (const float*)d_in[5];
    const float* W_dst    = (const float*)d_in[6];
    const float* b_dst    = (const float*)d_in[7];
    const float* W_a1     = (const float*)d_in[8];
    const float* b_a1     = (const float*)d_in[9];
    const float* W_a2     = (const float*)d_in[10];
    const float* b_a2     = (const float*)d_in[11];
    const float* W_out    = (const float*)d_in[12];
    const float* b_out    = (const float*)d_in[13];
    float* out = (float*)d_out;

    void *p_hs, *p_hd, *p_nf, *p_whi, *p_wlo, *p_den;
    cudaGetSymbolAddress(&p_hs, g_hs);
    cudaGetSymbolAddress(&p_hd, g_hd);
    cudaGetSymbolAddress(&p_nf, g_nf);
    cudaGetSymbolAddress(&p_whi, g_whi);
    cudaGetSymbolAddress(&p_wlo, g_wlo);
    cudaGetSymbolAddress(&p_den, g_denom);
    const __nv_bfloat16* whi = (const __nv_bfloat16*)p_whi;
    const __nv_bfloat16* wlo = (const __nv_bfloat16*)p_wlo;

    cudaFuncSetAttribute(k_gemm2<false>, cudaFuncAttributeMaxDynamicSharedMemorySize, SMEM_SZ);
    cudaFuncSetAttribute(k_gemm2<true>,  cudaFuncAttributeMaxDynamicSharedMemorySize, SMEM_SZ);
    cudaFuncSetAttribute(k_edge2,        cudaFuncAttributeMaxDynamicSharedMemorySize, SMEM_SZ);

    k_init_nf<<<(NDST * D + 255) / 256, 256>>>();                          // 0
    k_init_seg<<<(NDST + 255) / 256, 256>>>();                             // 1
    k_prep<<<(4 * D * D + 255) / 256, 256>>>(W_src, W_dst, W_a1, W_out);   // 2

    k_gemm2<false><<<NPERS, 256, SMEM_SZ>>>(                               // 3
        feat_src, nullptr, nullptr, whi + 0 * D * D, wlo + 0 * D * D, b_src, (float*)p_hs, NS);
    k_gemm2<false><<<NPERS, 256, SMEM_SZ>>>(                               // 4
        feat_dst, nullptr, nullptr, whi + 1 * D * D, wlo + 1 * D * D, b_dst, (float*)p_hd, NDST);

    k_edge2<<<NPERS, 256, SMEM_SZ>>>(                                      // 5
        src_idx, dst_idx, whi + 2 * D * D, wlo + 2 * D * D, b_a1, W_a2, b_a2);

    k_agg2<<<(NE * 32) / 256, 256>>>(src_idx, dst_idx);                    // 6

    k_gemm2<true><<<NPERS, 256, SMEM_SZ>>>(                                // 7
        (float*)p_nf, (const float*)p_hd, (const float*)p_den,
        whi + 3 * D * D, wlo + 3 * D * D, b_out, out, NDST);
}

// round 16
// speedup vs baseline: 1.5390x; 1.5390x over previous
#include <cuda_runtime.h>
#include <cuda_bf16.h>
#include <cuda_fp16.h>
#include <cstdint>

#define D     128
#define NS    50000
#define NDST  50000
#define NE    640000

// ---------------- scratch (static device arrays; no allocation) ----------------
__device__ __align__(16) float          g_hs[NS * D];
__device__ __align__(16) float          g_hd[NDST * D];
__device__ __align__(16) float          g_nf[NDST * D];
__device__ float          g_s[NE];
__device__ float          g_denom[NDST];
__device__ unsigned       g_mkey[NDST];
// 4 pre-split transposed weights: [which][n][k], bf16 hi/lo
__device__ __align__(16) __nv_bfloat16  g_whi[4 * D * D];
__device__ __align__(16) __nv_bfloat16  g_wlo[4 * D * D];
// fp16 copy of W_a1^T for the edge kernel (2-pass f16 path)
__device__ __align__(16) __half         g_wa1h[D * D];

__device__ __forceinline__ float lrelu(float x) { return x > 0.f ? x : 0.01f * x; }

__device__ __forceinline__ unsigned fenc(float f) {
    unsigned u = __float_as_uint(f);
    return (u & 0x80000000u) ? ~u : (u | 0x80000000u);
}
__device__ __forceinline__ float fdec(unsigned u) {
    return __uint_as_float((u & 0x80000000u) ? (u & 0x7FFFFFFFu) : ~u);
}

// ---------------- warp-mma helpers (generic PTX: sm_80+) ----------------
__device__ __forceinline__ uint32_t smem_u32(const void* p) {
    return (uint32_t)__cvta_generic_to_shared(p);
}
__device__ __forceinline__ void ldsm4(uint32_t* r, uint32_t addr) {
    asm volatile("ldmatrix.sync.aligned.m8n8.x4.shared.b16 {%0,%1,%2,%3}, [%4];"
                 : "=r"(r[0]), "=r"(r[1]), "=r"(r[2]), "=r"(r[3]) : "r"(addr));
}
__device__ __forceinline__ void mma16816(float* c, const uint32_t* a, const uint32_t* b) {
    asm volatile("mma.sync.aligned.m16n8k16.row.col.f32.bf16.bf16.f32 "
                 "{%0,%1,%2,%3}, {%4,%5,%6,%7}, {%8,%9}, {%0,%1,%2,%3};"
                 : "+f"(c[0]), "+f"(c[1]), "+f"(c[2]), "+f"(c[3])
                 : "r"(a[0]), "r"(a[1]), "r"(a[2]), "r"(a[3]), "r"(b[0]), "r"(b[1]));
}
__device__ __forceinline__ void mma16816h(float* c, const uint32_t* a, const uint32_t* b) {
    asm volatile("mma.sync.aligned.m16n8k16.row.col.f32.f16.f16.f32 "
                 "{%0,%1,%2,%3}, {%4,%5,%6,%7}, {%8,%9}, {%0,%1,%2,%3};"
                 : "+f"(c[0]), "+f"(c[1]), "+f"(c[2]), "+f"(c[3])
                 : "r"(a[0]), "r"(a[1]), "r"(a[2]), "r"(a[3]), "r"(b[0]), "r"(b[1]));
}
// split two fp32 into packed bf16x2 hi / lo (error compensation)
__device__ __forceinline__ void split2(float x, float y, uint32_t& h, uint32_t& l) {
    __nv_bfloat16 hx = __float2bfloat16(x);
    __nv_bfloat16 hy = __float2bfloat16(y);
    __nv_bfloat16 lx = __float2bfloat16(x - __bfloat162float(hx));
    __nv_bfloat16 ly = __float2bfloat16(y - __bfloat162float(hy));
    h = ((uint32_t)__bfloat16_as_ushort(hy) << 16) | __bfloat16_as_ushort(hx);
    l = ((uint32_t)__bfloat16_as_ushort(ly) << 16) | __bfloat16_as_ushort(lx);
}
// split two fp32 into packed f16x2 hi / lo (error compensation, 11-bit mantissa)
__device__ __forceinline__ void split2h(float x, float y, uint32_t& h, uint32_t& l) {
    __half hx = __float2half_rn(x);
    __half hy = __float2half_rn(y);
    __half lx = __float2half_rn(x - __half2float(hx));
    __half ly = __float2half_rn(y - __half2float(hy));
    h = ((uint32_t)__half_as_ushort(hy) << 16) | __half_as_ushort(hx);
    l = ((uint32_t)__half_as_ushort(ly) << 16) | __half_as_ushort(lx);
}
// swizzled byte offset of 16B unit (row, colUnit) in a [rows][128 x 2B] tile (256B rows)
__device__ __forceinline__ uint32_t uoff(int r, int cu) {
    return (uint32_t)(r * 256 + ((cu ^ (r & 7)) << 4));
}

// smem layouts
#define SMB_HI  0
#define SMB_LO  32768
#define SMB_AUX 65536
#define SMEM_SZ   (65536 + 1024)   // dense gemm: Bhi+Blo+aux
#define SMEM_EDGE (32768 + 1024)   // edge: Bh (fp16) + aux

// ---------------- init (single kernel) ----------------
__global__ void k_init() {
    int i = blockIdx.x * blockDim.x + threadIdx.x;
    if (i < NDST * D) g_nf[i] = 0.f;
    if (i < NDST) { g_denom[i] = 0.f; g_mkey[i] = 0u; }
}

// ---------------- prep: split all 4 W^T into bf16 hi/lo; also fp16 W_a1^T ----------------
__global__ void k_prep(const float* __restrict__ W0, const float* __restrict__ W1,
                       const float* __restrict__ W2, const float* __restrict__ W3)
{
    int i = blockIdx.x * blockDim.x + threadIdx.x;
    if (i >= 4 * D * D) return;
    int which = i >> 14;
    int j = i & (D * D - 1);
    int n = j >> 7, k = j & 127;
    const float* W = which == 0 ? W0 : which == 1 ? W1 : which == 2 ? W2 : W3;
    float w = W[k * D + n];
    __nv_bfloat16 hi = __float2bfloat16(w);
    __nv_bfloat16 lo = __float2bfloat16(w - __bfloat162float(hi));
    g_whi[i] = hi;
    g_wlo[i] = lo;
    if (which == 2) g_wa1h[j] = __float2half_rn(w);
}

// ---- bf16 3-pass mainloop body (dense GEMMs) ----
#define MAINLOOP_KK(c, Ahi_k, Alo_k)                                              \
    do {                                                                          \
        uint32_t bf[4][4];                                                        \
        _Pragma("unroll")                                                         \
        for (int p = 0; p < 4; p++) {                                             \
            int rowB = h * 64 + p * 16 + rBoff;                                   \
            uint32_t bo = (uint32_t)(rowB * 256 + (((kk * 2 + cB2) ^ rxB) << 4)); \
            ldsm4(bf[p], bhiB + bo);                                              \
        }                                                                         \
        _Pragma("unroll")                                                         \
        for (int p = 0; p < 4; p++) {                                             \
            mma16816(c[2 * p],     Ahi_k, bf[p]);                                 \
            mma16816(c[2 * p + 1], Ahi_k, bf[p] + 2);                             \
        }                                                                         \
        _Pragma("unroll")                                                         \
        for (int p = 0; p < 4; p++) {                                             \
            mma16816(c[2 * p],     Alo_k, bf[p]);                                 \
            mma16816(c[2 * p + 1], Alo_k, bf[p] + 2);                             \
        }                                                                         \
        _Pragma("unroll")                                                         \
        for (int p = 0; p < 4; p++) {                                             \
            int rowB = h * 64 + p * 16 + rBoff;                                   \
            uint32_t bo = (uint32_t)(rowB * 256 + (((kk * 2 + cB2) ^ rxB) << 4)); \
            ldsm4(bf[p], bloB + bo);                                              \
        }                                                                         \
        _Pragma("unroll")                                                         \
        for (int p = 0; p < 4; p++) {                                             \
            mma16816(c[2 * p],     Ahi_k, bf[p]);                                 \
            mma16816(c[2 * p + 1], Ahi_k, bf[p] + 2);                             \
        }                                                                         \
    } while (0)

// ---- f16 2-pass mainloop body (edge kernel): A exact (hi+lo), B single fp16 ----
#define MAINLOOP_KK_H(c, Ahi_k, Alo_k)                                            \
    do {                                                                          \
        uint32_t bf[4][4];                                                        \
        _Pragma("unroll")                                                         \
        for (int p = 0; p < 4; p++) {                                             \
            int rowB = h * 64 + p * 16 + rBoff;                                   \
            uint32_t bo = (uint32_t)(rowB * 256 + (((kk * 2 + cB2) ^ rxB) << 4)); \
            ldsm4(bf[p], bhB + bo);                                               \
        }                                                                         \
        _Pragma("unroll")                                                         \
        for (int p = 0; p < 4; p++) {                                             \
            mma16816h(c[2 * p],     Ahi_k, bf[p]);                                \
            mma16816h(c[2 * p + 1], Ahi_k, bf[p] + 2);                            \
        }                                                                         \
        _Pragma("unroll")                                                         \
        for (int p = 0; p < 4; p++) {                                             \
            mma16816h(c[2 * p],     Alo_k, bf[p]);                                \
            mma16816h(c[2 * p + 1], Alo_k, bf[p] + 2);                            \
        }                                                                         \
    } while (0)

// ---------------- dense GEMM, A loaded straight into fragments (R12 structure) ----------------
template<bool FINAL>
__global__ __launch_bounds__(256, 2) void k_gemm2(
    const float* __restrict__ A, const float* __restrict__ A2,
    const float* __restrict__ denom,
    const __nv_bfloat16* __restrict__ wh, const __nv_bfloat16* __restrict__ wl,
    const float* __restrict__ bias, float* __restrict__ C, int M)
{
    extern __shared__ char sm[];
    char*  Bhi = sm + SMB_HI;
    char*  Blo = sm + SMB_LO;
    float* sB  = (float*)(sm + SMB_AUX);

    int t = threadIdx.x, lane = t & 31, w = t >> 5;
    int m0 = blockIdx.x * 128;

    if (t < 128) sB[t] = bias[t];
    for (int i = t; i < 2048; i += 256) {
        int n = i >> 4, cu = i & 15;
        *(uint4*)(Bhi + uoff(n, cu)) = *(const uint4*)(wh + n * 128 + cu * 8);
        *(uint4*)(Blo + uoff(n, cu)) = *(const uint4*)(wl + n * 128 + cu * 8);
    }
    __syncthreads();

    int r0 = m0 + w * 16 + (lane >> 2);
    int r1 = r0 + 8;
    bool v0 = r0 < M, v1 = r1 < M;
    int cbase = (lane & 3) * 2;

    float sc0 = 1.f, sc1 = 1.f;
    bool add0 = false, add1 = false;
    if (FINAL) {
        float den0 = v0 ? __ldg(denom + r0) : 0.f;
        float den1 = v1 ? __ldg(denom + r1) : 0.f;
        add0 = den0 > 0.f; add1 = den1 > 0.f;
        sc0 = add0 ? 1.f / den0 : 0.f;
        sc1 = add1 ? 1.f / den1 : 0.f;
    }

    const float* a0p = A + (size_t)r0 * 128;
    const float* a1p = A + (size_t)r1 * 128;

    uint32_t Ahi[8][4], Alo[8][4];
#pragma unroll
    for (int k = 0; k < 8; k++) {
        int c0 = k * 16 + cbase, c1 = c0 + 8;
        float2 x00 = make_float2(0.f, 0.f), x10 = x00, x01 = x00, x11 = x00;
        if (v0) { x00 = *(const float2*)(a0p + c0); x01 = *(const float2*)(a0p + c1); }
        if (v1) { x10 = *(const float2*)(a1p + c0); x11 = *(const float2*)(a1p + c1); }
        if (FINAL) {
            const float* h0p = A2 + (size_t)r0 * 128;
            const float* h1p = A2 + (size_t)r1 * 128;
            float2 y00 = make_float2(0.f, 0.f), y10 = y00, y01 = y00, y11 = y00;
            if (add0) { y00 = *(const float2*)(h0p + c0); y01 = *(const float2*)(h0p + c1); }
            if (add1) { y10 = *(const float2*)(h1p + c0); y11 = *(const float2*)(h1p + c1); }
            x00.x = x00.x * sc0 + y00.x; x00.y = x00.y * sc0 + y00.y;
            x01.x = x01.x * sc0 + y01.x; x01.y = x01.y * sc0 + y01.y;
            x10.x = x10.x * sc1 + y10.x; x10.y = x10.y * sc1 + y10.y;
            x11.x = x11.x * sc1 + y11.x; x11.y = x11.y * sc1 + y11.y;
        }
        split2(x00.x, x00.y, Ahi[k][0], Alo[k][0]);
        split2(x10.x, x10.y, Ahi[k][1], Alo[k][1]);
        split2(x01.x, x01.y, Ahi[k][2], Alo[k][2]);
        split2(x11.x, x11.y, Ahi[k][3], Alo[k][3]);
    }

    int rBoff = ((lane >> 4) << 3) + (lane & 7);
    int cB2   = (lane >> 3) & 1;
    int rxB   = lane & 7;
    uint32_t bhiB = smem_u32(Bhi), bloB = smem_u32(Blo);

#pragma unroll
    for (int h = 0; h < 2; h++) {
        float c[8][4];
#pragma unroll
        for (int n2 = 0; n2 < 8; n2++)
#pragma unroll
            for (int q = 0; q < 4; q++) c[n2][q] = 0.f;

#pragma unroll
        for (int kk = 0; kk < 8; kk++) {
            MAINLOOP_KK(c, Ahi[kk], Alo[kk]);
        }
#pragma unroll
        for (int n2 = 0; n2 < 8; n2++) {
            int n0 = (h * 8 + n2) * 8 + cbase;
            float b0 = sB[n0], b1 = sB[n0 + 1];
            float v00 = c[n2][0] + b0, v01 = c[n2][1] + b1;
            float v10 = c[n2][2] + b0, v11 = c[n2][3] + b1;
            if (FINAL) { v00 = lrelu(v00); v01 = lrelu(v01); v10 = lrelu(v10); v11 = lrelu(v11); }
            if (v0) *(float2*)(C + (size_t)r0 * 128 + n0) = make_float2(v00, v01);
            if (v1) *(float2*)(C + (size_t)r1 * 128 + n0) = make_float2(v10, v11);
        }
    }
}

// ---------------- edge score: 128 edges/CTA, fp16 2-pass, A gathered into fragments ----------------
__global__ __launch_bounds__(256, 2) void k_edge2(
    const int* __restrict__ src_idx, const int* __restrict__ dst_idx,
    const __half* __restrict__ wah,
    const float* __restrict__ b_a1, const float* __restrict__ W_a2,
    const float* __restrict__ b_a2)
{
    extern __shared__ char sm[];
    char*  Bh   = sm;
    float* sBa1 = (float*)(sm + 32768);
    float* sWa2 = (float*)(sm + 32768 + 512);

    int t = threadIdx.x, lane = t & 31, w = t >> 5;
    int e0 = blockIdx.x * 128;

    if (t < 128) { sBa1[t] = b_a1[t]; sWa2[t] = W_a2[t]; }
    for (int i = t; i < 2048; i += 256) {
        int n = i >> 4, cu = i & 15;
        *(uint4*)(Bh + uoff(n, cu)) = *(const uint4*)(wah + n * 128 + cu * 8);
    }
    __syncthreads();

    int r0 = w * 16 + (lane >> 2);
    int r1 = r0 + 8;
    int s0 = __ldg(src_idx + e0 + r0), s1 = __ldg(src_idx + e0 + r1);
    int d0 = __ldg(dst_idx + e0 + r0), d1 = __ldg(dst_idx + e0 + r1);
    int cbase = (lane & 3) * 2;
    float ba2 = __ldg(b_a2);

    const float* hs0 = g_hs + (size_t)s0 * 128;
    const float* hs1 = g_hs + (size_t)s1 * 128;
    const float* hd0 = g_hd + (size_t)d0 * 128;
    const float* hd1 = g_hd + (size_t)d1 * 128;

    uint32_t Ahi[8][4], Alo[8][4];
#pragma unroll
    for (int k = 0; k < 8; k++) {
        int c0 = k * 16 + cbase, c1 = c0 + 8;
        float2 a00 = *(const float2*)(hs0 + c0), b00 = *(const float2*)(hd0 + c0);
        float2 a10 = *(const float2*)(hs1 + c0), b10 = *(const float2*)(hd1 + c0);
        float2 a01 = *(const float2*)(hs0 + c1), b01 = *(const float2*)(hd0 + c1);
        float2 a11 = *(const float2*)(hs1 + c1), b11 = *(const float2*)(hd1 + c1);
        split2h(lrelu(a00.x + b00.x), lrelu(a00.y + b00.y), Ahi[k][0], Alo[k][0]);
        split2h(lrelu(a10.x + b10.x), lrelu(a10.y + b10.y), Ahi[k][1], Alo[k][1]);
        split2h(lrelu(a01.x + b01.x), lrelu(a01.y + b01.y), Ahi[k][2], Alo[k][2]);
        split2h(lrelu(a11.x + b11.x), lrelu(a11.y + b11.y), Ahi[k][3], Alo[k][3]);
    }

    int rBoff = ((lane >> 4) << 3) + (lane & 7);
    int cB2   = (lane >> 3) & 1;
    int rxB   = lane & 7;
    uint32_t bhB = smem_u32(Bh);

    float rs0 = 0.f, rs1 = 0.f;

#pragma unroll
    for (int h = 0; h < 2; h++) {
        float c[8][4];
#pragma unroll
        for (int n2 = 0; n2 < 8; n2++)
#pragma unroll
            for (int q = 0; q < 4; q++) c[n2][q] = 0.f;

#pragma unroll
        for (int kk = 0; kk < 8; kk++) {
            MAINLOOP_KK_H(c, Ahi[kk], Alo[kk]);
        }
#pragma unroll
        for (int n2 = 0; n2 < 8; n2++) {
            int n0 = (h * 8 + n2) * 8 + cbase;
            float b0 = sBa1[n0], b1 = sBa1[n0 + 1];
            float w0 = sWa2[n0], w1 = sWa2[n0 + 1];
            rs0 += lrelu(c[n2][0] + b0) * w0 + lrelu(c[n2][1] + b1) * w1;
            rs1 += lrelu(c[n2][2] + b0) * w0 + lrelu(c[n2][3] + b1) * w1;
        }
    }

    rs0 += __shfl_xor_sync(0xffffffffu, rs0, 1);
    rs0 += __shfl_xor_sync(0xffffffffu, rs0, 2);
    rs1 += __shfl_xor_sync(0xffffffffu, rs1, 1);
    rs1 += __shfl_xor_sync(0xffffffffu, rs1, 2);

    if ((lane & 3) == 0) {
        float sv0 = rs0 + ba2, sv1 = rs1 + ba2;
        g_s[e0 + r0] = sv0;
        g_s[e0 + r1] = sv1;
        atomicMax(&g_mkey[d0], fenc(sv0));
        atomicMax(&g_mkey[d1], fenc(sv1));
    }
}

// ---------------- fused exp + aggregation: nf[d] += ex*hs[src]; denom[d] += ex ----------------
__global__ __launch_bounds__(256) void k_agg2(
    const int* __restrict__ src_idx, const int* __restrict__ dst_idx)
{
    int gt   = blockIdx.x * blockDim.x + threadIdx.x;
    int e    = gt >> 5;
    int lane = gt & 31;
    if (e >= NE) return;
    int s = __ldg(src_idx + e), d = __ldg(dst_idx + e);
    float ex = expf(__ldg(g_s + e) - fdec(g_mkey[d]));
    if (lane == 0) atomicAdd(&g_denom[d], ex);

    const float4* hs4 = (const float4*)g_hs;
    float4 a = hs4[s * 32 + lane];
    float4 v = make_float4(ex * a.x, ex * a.y, ex * a.z, ex * a.w);

    float* p = g_nf + d * 128 + lane * 4;
    asm volatile("red.global.add.v4.f32 [%0], {%1, %2, %3, %4};"
                 :: "l"(p), "f"(v.x), "f"(v.y), "f"(v.z), "f"(v.w) : "memory");
}

// ---------------- launch ----------------
extern "C" void kernel_launch(void* const* d_in, const int* in_sizes, int n_in,
                              void* d_out, int out_size)
{
    const float* feat_src = (const float*)d_in[0];
    const float* feat_dst = (const float*)d_in[1];
    const int*   src_idx  = (const int*)d_in[2];
    const int*   dst_idx  = (const int*)d_in[3];
    const float* W_src    = (const float*)d_in[4];
    const float* b_src    = (const float*)d_in[5];
    const float* W_dst    = (const float*)d_in[6];
    const float* b_dst    = (const float*)d_in[7];
    const float* W_a1     = (const float*)d_in[8];
    const float* b_a1     = (const float*)d_in[9];
    const float* W_a2     = (const float*)d_in[10];
    const float* b_a2     = (const float*)d_in[11];
    const float* W_out    = (const float*)d_in[12];
    const float* b_out    = (const float*)d_in[13];
    float* out = (float*)d_out;

    void *p_hs, *p_hd, *p_nf, *p_whi, *p_wlo, *p_den, *p_wah;
    cudaGetSymbolAddress(&p_hs, g_hs);
    cudaGetSymbolAddress(&p_hd, g_hd);
    cudaGetSymbolAddress(&p_nf, g_nf);
    cudaGetSymbolAddress(&p_whi, g_whi);
    cudaGetSymbolAddress(&p_wlo, g_wlo);
    cudaGetSymbolAddress(&p_den, g_denom);
    cudaGetSymbolAddress(&p_wah, g_wa1h);
    const __nv_bfloat16* whi = (const __nv_bfloat16*)p_whi;
    const __nv_bfloat16* wlo = (const __nv_bfloat16*)p_wlo;

    cudaFuncSetAttribute(k_gemm2<false>, cudaFuncAttributeMaxDynamicSharedMemorySize, SMEM_SZ);
    cudaFuncSetAttribute(k_gemm2<true>,  cudaFuncAttributeMaxDynamicSharedMemorySize, SMEM_SZ);
    cudaFuncSetAttribute(k_edge2,        cudaFuncAttributeMaxDynamicSharedMemorySize, SMEM_EDGE);

    k_init<<<(NDST * D + 255) / 256, 256>>>();                             // 0
    k_prep<<<(4 * D * D + 255) / 256, 256>>>(W_src, W_dst, W_a1, W_out);   // 1

    k_gemm2<false><<<(NS + 127) / 128, 256, SMEM_SZ>>>(                    // 2
        feat_src, nullptr, nullptr, whi + 0 * D * D, wlo + 0 * D * D, b_src, (float*)p_hs, NS);
    k_gemm2<false><<<(NDST + 127) / 128, 256, SMEM_SZ>>>(                  // 3
        feat_dst, nullptr, nullptr, whi + 1 * D * D, wlo + 1 * D * D, b_dst, (float*)p_hd, NDST);

    k_edge2<<<NE / 128, 256, SMEM_EDGE>>>(                                 // 4
        src_idx, dst_idx, (const __half*)p_wah, b_a1, W_a2, b_a2);

    k_agg2<<<(NE * 32) / 256, 256>>>(src_idx, dst_idx);                    // 5

    k_gemm2<true><<<(NDST + 127) / 128, 256, SMEM_SZ>>>(                   // 6
        (float*)p_nf, (const float*)p_hd, (const float*)p_den,
        whi + 3 * D * D, wlo + 3 * D * D, b_out, out, NDST);
}